// round 4
// baseline (speedup 1.0000x reference)
#include <cuda_runtime.h>
#include <cstdint>
#include <cstddef>

#define LL 32
#define HH 128
#define KD 130
#define KP 136            // padded row stride (floats); 136%32==8 -> conflict-free LDS.128
#define KPH 68            // K-half per thread
#define SPB 4
#define NBLK 128
#define NTHR 256
#define NCELL 1024
#define EPSF 1e-8f
#define W_BYTES  (HH * KP * 4u)   // 69632
#define SM_BYTES 512u
#define TX_BYTES (W_BYTES + 2u * SM_BYTES)

typedef unsigned long long ull;
struct __align__(16) u64x2 { ull x, y; };

__device__ float g_Wp[(size_t)NCELL * HH * KP];

struct __align__(16) Smem {
    float W[2][HH * KP];          // 139264
    float bvec[2][HH];            //   1024
    float wfvec[2][HH];           //   1024
    float4 hv4[LL][HH];           //  65536  (per-col, per-neuron, 4 samples packed)
    float inp[2][KP][SPB];        //   4352
    float red[2][8][SPB];         //    256
    float pre[NCELL][SPB];        //  16384
    uint32_t sbits[SPB][LL];      //    512
    ull mbar[2];                  //     16
};                                // 228368 B

__device__ __forceinline__ uint32_t s2u(const void* p) {
    return (uint32_t)__cvta_generic_to_shared(p);
}
__device__ __forceinline__ void mbar_init(uint32_t a, uint32_t cnt) {
    asm volatile("mbarrier.init.shared::cta.b64 [%0], %1;" :: "r"(a), "r"(cnt) : "memory");
}
__device__ __forceinline__ void mbar_expect(uint32_t a, uint32_t tx) {
    asm volatile("mbarrier.arrive.expect_tx.shared::cta.b64 _, [%0], %1;" :: "r"(a), "r"(tx) : "memory");
}
__device__ __forceinline__ void tma1d(uint32_t dst, const void* src, uint32_t bytes, uint32_t mbar) {
    asm volatile("cp.async.bulk.shared::cluster.global.mbarrier::complete_tx::bytes [%0], [%1], %2, [%3];"
                 :: "r"(dst), "l"(src), "r"(bytes), "r"(mbar) : "memory");
}
__device__ __forceinline__ void mbar_wait(uint32_t a, uint32_t phase) {
    uint32_t done = 0;
    while (!done) {
        asm volatile("{\n\t.reg .pred p;\n\t"
                     "mbarrier.try_wait.parity.acquire.cta.shared::cta.b64 p, [%1], %2;\n\t"
                     "selp.b32 %0, 1, 0, p;\n\t}"
                     : "=r"(done) : "r"(a), "r"(phase) : "memory");
    }
}
__device__ __forceinline__ float tanh_fast(float x) {
    float y; asm("tanh.approx.f32 %0, %1;" : "=f"(y) : "f"(x)); return y;
}
__device__ __forceinline__ ull pack2(float w) {
    ull r; asm("mov.b64 %0, {%1, %1};" : "=l"(r) : "f"(w)); return r;
}
__device__ __forceinline__ void fma2(ull& a, ull w, ull b) {
    asm("fma.rn.f32x2 %0, %1, %2, %0;" : "+l"(a) : "l"(w), "l"(b));
}
__device__ __forceinline__ ull add2(ull a, ull b) {
    ull r; asm("add.rn.f32x2 %0, %1, %2;" : "=l"(r) : "l"(a), "l"(b)); return r;
}
__device__ __forceinline__ void unpack2(ull v, float& lo, float& hi) {
    unsigned l, h;
    asm("mov.b64 {%0, %1}, %2;" : "=r"(l), "=r"(h) : "l"(v));
    lo = __uint_as_float(l); hi = __uint_as_float(h);
}

// ---------------- prep: pad fp32 W rows 130 -> 136 ----------------
__global__ void prep_kernel(const float* __restrict__ gW) {
    const int c = blockIdx.x;
    const float* src = gW + (size_t)c * (HH * KD);
    float* dst = g_Wp + (size_t)c * (HH * KP);
    for (int t = threadIdx.x; t < HH * KP; t += blockDim.x) {
        const int row = t / KP, col = t - row * KP;
        dst[t] = (col < KD) ? src[row * KD + col] : 0.f;
    }
}

// ---------------- main persistent kernel ----------------
__global__ void __launch_bounds__(NTHR, 1)
rnn2d_kernel(const float* __restrict__ gS, const float* __restrict__ gB,
             const float* __restrict__ gWf, const float* __restrict__ gBf,
             float* __restrict__ out)
{
    extern __shared__ unsigned char smem_raw[];
    Smem& s = *reinterpret_cast<Smem*>(smem_raw);
    const int tid = threadIdx.x;
    const int blk = blockIdx.x;
    const int n   = tid >> 1;      // neuron
    const int hh  = tid & 1;       // K-half
    const int lid = tid & 31;
    const int wid = tid >> 5;

    // ---- init ----
    const float* gs = gS + (size_t)blk * SPB * NCELL;
    if (tid < SPB * LL) {
        const int sm = tid >> 5, row = tid & 31;
        const float* rp = gs + sm * NCELL + row * LL;
        uint32_t bits = 0;
        #pragma unroll
        for (int j = 0; j < LL; ++j) bits |= (rp[j] > 0.5f ? 1u : 0u) << j;
        s.sbits[sm][row] = bits;
    }
    for (int t = tid; t < LL * HH; t += NTHR)
        ((float4*)s.hv4)[t] = make_float4(0.f, 0.f, 0.f, 0.f);
    for (int t = tid; t < 2 * KP * SPB; t += NTHR) ((float*)s.inp)[t] = 0.f;
    __syncthreads();
    if (tid == 0)
        *(float4*)&s.inp[0][1][0] = make_float4(2.f, 2.f, 2.f, 2.f);

    const uint32_t mb0 = s2u(&s.mbar[0]);
    const uint32_t mb1 = s2u(&s.mbar[1]);
    if (tid == 0) {
        mbar_init(mb0, 1);
        mbar_init(mb1, 1);
        asm volatile("fence.mbarrier_init.release.cluster;" ::: "memory");
    }
    __syncthreads();

    if (tid == 0) {
        mbar_expect(mb0, TX_BYTES);
        tma1d(s2u(&s.W[0][0]),     g_Wp, W_BYTES,  mb0);
        tma1d(s2u(&s.bvec[0][0]),  gB,   SM_BYTES, mb0);
        tma1d(s2u(&s.wfvec[0][0]), gWf,  SM_BYTES, mb0);
    }

    for (int c = 0; c < NCELL; ++c) {
        const int buf = c & 1;
        const int r = c >> 5, j = c & 31;
        const int col = (r & 1) ? (LL - 1 - j) : j;
        const int cell = (r << 5) + col;

        if (tid == 0 && c + 1 < NCELL) {
            const int cn = c + 1, rn = cn >> 5, jn = cn & 31;
            const int coln = (rn & 1) ? (LL - 1 - jn) : jn;
            const int celln = (rn << 5) + coln;
            const uint32_t mb = buf ? mb0 : mb1;
            mbar_expect(mb, TX_BYTES);
            tma1d(s2u(&s.W[buf ^ 1][0]),     g_Wp + (size_t)celln * HH * KP, W_BYTES,  mb);
            tma1d(s2u(&s.bvec[buf ^ 1][0]),  gB  + celln * HH,               SM_BYTES, mb);
            tma1d(s2u(&s.wfvec[buf ^ 1][0]), gWf + celln * HH,               SM_BYTES, mb);
        }
        mbar_wait(buf ? mb1 : mb0, (c >> 1) & 1);

        // ---- half-matvec: thread (n, hh), packed f32x2 over sample pairs ----
        const float* Wr = &s.W[buf][n * KP + hh * KPH];
        const float (*ipr)[SPB] = &s.inp[buf][hh * KPH];
        ull a01 = 0ull, a23 = 0ull;
        #pragma unroll
        for (int i = 0; i < KPH; i += 4) {
            const float4 w = *(const float4*)(Wr + i);
            const u64x2 p0 = *(const u64x2*)&ipr[i + 0][0];
            const u64x2 p1 = *(const u64x2*)&ipr[i + 1][0];
            const u64x2 p2 = *(const u64x2*)&ipr[i + 2][0];
            const u64x2 p3 = *(const u64x2*)&ipr[i + 3][0];
            const ull w0 = pack2(w.x), w1 = pack2(w.y);
            const ull w2 = pack2(w.z), w3 = pack2(w.w);
            fma2(a01, w0, p0.x); fma2(a23, w0, p0.y);
            fma2(a01, w1, p1.x); fma2(a23, w1, p1.y);
            fma2(a01, w2, p2.x); fma2(a23, w2, p2.y);
            fma2(a01, w3, p3.x); fma2(a23, w3, p3.y);
        }
        // combine the two K-halves (adjacent lanes)
        a01 = add2(a01, __shfl_xor_sync(0xffffffffu, a01, 1));
        a23 = add2(a23, __shfl_xor_sync(0xffffffffu, a23, 1));

        float sv0, sv1, sv2, sv3;
        unpack2(a01, sv0, sv1);
        unpack2(a23, sv2, sv3);
        const float bi2 = 2.f * s.bvec[buf][n];
        const float h0 = tanh_fast(sv0 + bi2), h1 = tanh_fast(sv1 + bi2);
        const float h2 = tanh_fast(sv2 + bi2), h3 = tanh_fast(sv3 + bi2);

        // ---- fc-head: lane hh handles samples (2hh, 2hh+1) ----
        const float wfi = s.wfvec[buf][n];
        float pA = wfi * (hh ? h2 : h0);
        float pB = wfi * (hh ? h3 : h1);
        #pragma unroll
        for (int o = 2; o <= 16; o <<= 1) {
            pA += __shfl_xor_sync(0xffffffffu, pA, o);
            pB += __shfl_xor_sync(0xffffffffu, pB, o);
        }
        if (lid < 2) {
            s.red[buf][wid][2 * lid + 0] = pA;
            s.red[buf][wid][2 * lid + 1] = pB;
        }

        // ---- hv update + next-cell input build (hh==0 lanes) ----
        if (hh == 0) {
            const float4 hvv = make_float4(h0, h1, h2, h3);
            s.hv4[col][n] = hvv;
            if (c + 1 < NCELL) {
                const int cn = c + 1, rn = cn >> 5, jn = cn & 31;
                const int coln = (rn & 1) ? (LL - 1 - jn) : jn;
                float4 v;
                if (jn == 0) {
                    v = hvv;   // coln == col: h_v is the value just computed
                } else {
                    const float4 t = s.hv4[coln][n];   // written last row
                    v = make_float4(h0 + t.x, h1 + t.y, h2 + t.z, h3 + t.w);
                }
                *(float4*)&s.inp[buf ^ 1][2 + n][0] = v;
            }
        }
        if (tid == 0 && c + 1 < NCELL) {
            const int cn = c + 1, rn = cn >> 5, jn = cn & 31;
            const int coln = (rn & 1) ? (LL - 1 - jn) : jn;
            float4 e0, e1;
            float* x0 = &e0.x; float* x1 = &e1.x;
            #pragma unroll
            for (int si = 0; si < SPB; ++si) {
                const float xh = (jn == 0) ? 0.f : (float)((s.sbits[si][rn] >> col) & 1u);
                const float xv = (rn == 0) ? 0.f : (float)((s.sbits[si][rn - 1] >> coln) & 1u);
                x0[si] = xh + xv;
                x1[si] = 2.f - xh - xv;
            }
            *(float4*)&s.inp[buf ^ 1][0][0] = e0;
            *(float4*)&s.inp[buf ^ 1][1][0] = e1;
        }
        __syncthreads();

        if (tid < SPB) {
            float acc = 0.f;
            #pragma unroll
            for (int w = 0; w < 8; ++w) acc += s.red[buf][w][tid];
            s.pre[cell][tid] = acc;
        }
    }

    // ---------------- bulk log-prob pass ----------------
    __syncthreads();
    float lp0 = 0.f, lp1 = 0.f, lp2 = 0.f, lp3 = 0.f;
    for (int c = tid; c < NCELL; c += NTHR) {
        const float bfv = __ldg(gBf + c);
        const float4 pr = *(const float4*)&s.pre[c][0];
        const int row = c >> 5, bit = c & 31;
        {
            const float z = pr.x + bfv;
            const float xh = 1.f / (1.f + __expf(-z));
            const float m = (float)((s.sbits[0][row] >> bit) & 1u);
            lp0 += m * __logf(xh + EPSF) + (1.f - m) * __logf(1.f - xh + EPSF);
        }
        {
            const float z = pr.y + bfv;
            const float xh = 1.f / (1.f + __expf(-z));
            const float m = (float)((s.sbits[1][row] >> bit) & 1u);
            lp1 += m * __logf(xh + EPSF) + (1.f - m) * __logf(1.f - xh + EPSF);
        }
        {
            const float z = pr.z + bfv;
            const float xh = 1.f / (1.f + __expf(-z));
            const float m = (float)((s.sbits[2][row] >> bit) & 1u);
            lp2 += m * __logf(xh + EPSF) + (1.f - m) * __logf(1.f - xh + EPSF);
        }
        {
            const float z = pr.w + bfv;
            const float xh = 1.f / (1.f + __expf(-z));
            const float m = (float)((s.sbits[3][row] >> bit) & 1u);
            lp3 += m * __logf(xh + EPSF) + (1.f - m) * __logf(1.f - xh + EPSF);
        }
    }
    #pragma unroll
    for (int o = 16; o; o >>= 1) {
        lp0 += __shfl_xor_sync(0xffffffffu, lp0, o);
        lp1 += __shfl_xor_sync(0xffffffffu, lp1, o);
        lp2 += __shfl_xor_sync(0xffffffffu, lp2, o);
        lp3 += __shfl_xor_sync(0xffffffffu, lp3, o);
    }
    if (lid == 0) {
        s.red[0][wid][0] = lp0; s.red[0][wid][1] = lp1;
        s.red[0][wid][2] = lp2; s.red[0][wid][3] = lp3;
    }
    __syncthreads();
    if (tid < SPB) {
        float acc = 0.f;
        #pragma unroll
        for (int w = 0; w < 8; ++w) acc += s.red[0][w][tid];
        out[blk * SPB + tid] = acc;
    }
}

extern "C" void kernel_launch(void* const* d_in, const int* in_sizes, int n_in,
                              void* d_out, int out_size) {
    const float* samples = (const float*)d_in[0];
    const float* W1      = (const float*)d_in[1];
    const float* b1      = (const float*)d_in[2];
    const float* Wf      = (const float*)d_in[3];
    const float* bf      = (const float*)d_in[4];
    float* out = (float*)d_out;

    prep_kernel<<<NCELL, 256>>>(W1);

    const size_t smem = sizeof(Smem);
    cudaFuncSetAttribute(rnn2d_kernel, cudaFuncAttributeMaxDynamicSharedMemorySize, (int)smem);
    rnn2d_kernel<<<NBLK, NTHR, smem>>>(samples, b1, Wf, bf, out);
}